// round 16
// baseline (speedup 1.0000x reference)
#include <cuda_runtime.h>
#include <cuda_fp16.h>
#include <math.h>
#include <stdint.h>

// Problem constants
#define BB 2
#define TT 2048
#define CD 768
#define HH 12
#define HDIM 64
#define DD2 32
#define FFD 3072
#define NROWS (BB*TT)          // 4096
static __device__ __constant__ float kEPS = 1e-5f;
#define LOG2E 1.44269504088896340736f

// ---------------- scratch ----------------
__device__ __half g_h [NROWS*CD];
__device__ __half g_q [NROWS*CD];
__device__ __half g_k [NROWS*CD];
__device__ __half g_v [NROWS*CD];
__device__ __half g_y [NROWS*CD];
__device__ __half g_ff[NROWS*FFD];
__device__ float  g_x2[NROWS*CD];
__device__ __half g_wqt [CD*CD];
__device__ __half g_wkt [CD*CD];
__device__ __half g_wvt [CD*CD];
__device__ __half g_wot [CD*CD];
__device__ __half g_wfct[FFD*CD];
__device__ __half g_wprt[CD*FFD];

// ---------------- helpers ----------------
__device__ __forceinline__ void mma_f16(float* c, const uint32_t* a, const uint32_t* b) {
    asm volatile(
        "mma.sync.aligned.m16n8k16.row.col.f32.f16.f16.f32 "
        "{%0,%1,%2,%3}, {%4,%5,%6,%7}, {%8,%9}, {%0,%1,%2,%3};"
        : "+f"(c[0]), "+f"(c[1]), "+f"(c[2]), "+f"(c[3])
        : "r"(a[0]), "r"(a[1]), "r"(a[2]), "r"(a[3]), "r"(b[0]), "r"(b[1]));
}
__device__ __forceinline__ void ldsm4(uint32_t* r, uint32_t addr) {
    asm volatile("ldmatrix.sync.aligned.m8n8.x4.shared.b16 {%0,%1,%2,%3}, [%4];"
                 : "=r"(r[0]), "=r"(r[1]), "=r"(r[2]), "=r"(r[3]) : "r"(addr));
}
__device__ __forceinline__ void ldsm4t(uint32_t* r, uint32_t addr) {
    asm volatile("ldmatrix.sync.aligned.m8n8.x4.trans.shared.b16 {%0,%1,%2,%3}, [%4];"
                 : "=r"(r[0]), "=r"(r[1]), "=r"(r[2]), "=r"(r[3]) : "r"(addr));
}
__device__ __forceinline__ uint32_t smem_u32(const void* p) {
    uint32_t a;
    asm("{ .reg .u64 t; cvta.to.shared.u64 t, %1; cvt.u32.u64 %0, t; }" : "=r"(a) : "l"(p));
    return a;
}
__device__ __forceinline__ void cp16(uint32_t dst, const void* src) {
    asm volatile("cp.async.cg.shared.global [%0], [%1], 16;" :: "r"(dst), "l"(src));
}
#define CP_COMMIT() asm volatile("cp.async.commit_group;" ::: "memory")
#define CP_WAIT1()  asm volatile("cp.async.wait_group 1;" ::: "memory")
#define CP_WAIT0()  asm volatile("cp.async.wait_group 0;" ::: "memory")
__device__ __forceinline__ uint32_t packh2(float a, float b) {
    __half2 h = __floats2half2_rn(a, b);
    return *(uint32_t*)&h;
}

// ---------------- batched weight transpose+convert ----------------
__global__ __launch_bounds__(256) void transp_all(
    const float* __restrict__ wq, const float* __restrict__ wk,
    const float* __restrict__ wv, const float* __restrict__ wo,
    const float* __restrict__ wfc, const float* __restrict__ wpr,
    __half* __restrict__ wqt, __half* __restrict__ wkt,
    __half* __restrict__ wvt, __half* __restrict__ wot,
    __half* __restrict__ wfct, __half* __restrict__ wprt) {
    const int z = blockIdx.z, a = blockIdx.x, b = blockIdx.y;
    const float* src; __half* dst; int R, C, c0, r0;
    if (z < 4) {
        if (a >= 24) return;
        src = (z == 0) ? wq : (z == 1) ? wk : (z == 2) ? wv : wo;
        dst = (z == 0) ? wqt : (z == 1) ? wkt : (z == 2) ? wvt : wot;
        R = CD; C = CD; c0 = a * 32; r0 = b * 32;
    } else if (z == 4) {
        src = wfc; dst = wfct; R = CD; C = FFD; c0 = a * 32; r0 = b * 32;
    } else {
        src = wpr; dst = wprt; R = FFD; C = CD; c0 = b * 32; r0 = a * 32;
    }
    __shared__ float t[32][33];
    const int tx = threadIdx.x & 31, ty = threadIdx.x >> 5;
    #pragma unroll
    for (int p = 0; p < 4; p++)
        t[ty + p * 8][tx] = src[(size_t)(r0 + ty + p * 8) * C + c0 + tx];
    __syncthreads();
    #pragma unroll
    for (int p = 0; p < 4; p++)
        dst[(size_t)(c0 + ty + p * 8) * R + r0 + tx] = __float2half_rn(t[tx][ty + p * 8]);
}

// SMEM geometry
#define STH 72
#define ROWB 144
// swizzled BN=64: exact 128B rows
#define A64_B (128 * 128)               // 16384
#define B64_B (64 * 128)                // 8192
#define STAGE64_B (A64_B + B64_B)       // 24576
#define NSTAGE 3
#define GEMM64_SMEM (NSTAGE * STAGE64_B) // 73728

// ============ fp16 GEMM core BN=64, XOR-swizzled, 3 CTAs/SM ============
__device__ __forceinline__ void gemm_mainloop64(const __half* __restrict__ A,
                                                const __half* __restrict__ Wt,
                                                int K, int bm, int bn, char* sm,
                                                float c64[2][4][4]) {
    const int tid = threadIdx.x;
    const int warp = tid >> 5, lane = tid & 31;
    const int wy = warp >> 1, wx = warp & 1;

    #pragma unroll
    for (int i = 0; i < 2; i++)
        #pragma unroll
        for (int j = 0; j < 4; j++)
            #pragma unroll
            for (int t = 0; t < 4; t++) c64[i][j][t] = 0.f;

    const int NC = K >> 6;
    const uint32_t sbase = smem_u32(sm);

    const int rowA = tid >> 1, gA = (tid & 1) * 4;
    const __half* Ab = A + (size_t)(bm + rowA) * K + gA * 8;
    const uint32_t aRow = (uint32_t)rowA * 128;
    const int aMsk = rowA & 7;
    const int rowB = tid >> 2, gB = (tid & 3) * 2;
    const __half* Bb = Wt + (size_t)(bn + rowB) * K + gB * 8;
    const uint32_t bRow = (uint32_t)(A64_B + rowB * 128);
    const int bMsk = rowB & 7;

    const int l7 = lane & 7;
    const int rA = wy * 32 + ((lane >> 3) & 1) * 8 + l7;
    const int cA = lane >> 4;
    const int mA = rA & 7;
    const int rB = wx * 32 + ((lane >> 4) & 1) * 8 + l7;
    const int cB = (lane >> 3) & 1;
    const int mB = rB & 7;

    #pragma unroll
    for (int s = 0; s < 2; s++) {
        const uint32_t st = sbase + s * STAGE64_B;
        #pragma unroll
        for (int p = 0; p < 4; p++)
            cp16(st + aRow + (((gA + p) ^ aMsk) * 16), Ab + s * 64 + p * 8);
        #pragma unroll
        for (int p = 0; p < 2; p++)
            cp16(st + bRow + (((gB + p) ^ bMsk) * 16), Bb + s * 64 + p * 8);
        CP_COMMIT();
    }

    int s = 0;
    for (int c = 0; c < NC; c++) {
        CP_WAIT1();
        __syncthreads();
        if (c + 2 < NC) {
            const int s2 = (s + 2 >= NSTAGE) ? s + 2 - NSTAGE : s + 2;
            const uint32_t st = sbase + s2 * STAGE64_B;
            #pragma unroll
            for (int p = 0; p < 4; p++)
                cp16(st + aRow + (((gA + p) ^ aMsk) * 16), Ab + (c + 2) * 64 + p * 8);
            #pragma unroll
            for (int p = 0; p < 2; p++)
                cp16(st + bRow + (((gB + p) ^ bMsk) * 16), Bb + (c + 2) * 64 + p * 8);
        }
        CP_COMMIT();

        const uint32_t stA = sbase + s * STAGE64_B;
        const uint32_t stB = stA + A64_B;
        #pragma unroll
        for (int ks = 0; ks < 4; ks++) {
            uint32_t af[2][4], bf[2][4];
            const uint32_t ca = (uint32_t)(((cA + 2 * ks) ^ mA) * 16);
            ldsm4(af[0], stA + (uint32_t)rA * 128 + ca);
            ldsm4(af[1], stA + (uint32_t)(rA + 16) * 128 + ca);
            const uint32_t cb = (uint32_t)(((cB + 2 * ks) ^ mB) * 16);
            ldsm4(bf[0], stB + (uint32_t)rB * 128 + cb);
            ldsm4(bf[1], stB + (uint32_t)(rB + 16) * 128 + cb);
            #pragma unroll
            for (int i = 0; i < 2; i++)
                #pragma unroll
                for (int j = 0; j < 4; j++)
                    mma_f16(c64[i][j], af[i], &bf[j >> 1][(j & 1) * 2]);
        }
        s = (s + 1 >= NSTAGE) ? 0 : s + 1;
    }
}

// ============ GEMM kernels (wo/fc/pr) ============
template <int EPI>
__global__ __launch_bounds__(256, 3) void gemm64_f16(const __half* __restrict__ A,
                                                     const __half* __restrict__ Wt,
                                                     const float* __restrict__ R,
                                                     void* __restrict__ OutV,
                                                     int N, int K) {
    extern __shared__ char sm[];
    const int bm = blockIdx.y * 128, bn = blockIdx.x * 64;
    float c64[2][4][4];
    gemm_mainloop64(A, Wt, K, bm, bn, sm, c64);

    const int tid = threadIdx.x;
    const int warp = tid >> 5, lane = tid & 31;
    const int wy = warp >> 1, wx = warp & 1;
    const int gid = lane >> 2, tig = lane & 3;

    #pragma unroll
    for (int i = 0; i < 2; i++) {
        const int r0 = bm + wy * 32 + i * 16 + gid;
        const int r1 = r0 + 8;
        #pragma unroll
        for (int j = 0; j < 4; j++) {
            const int cc = bn + wx * 32 + j * 8 + 2 * tig;
            float v0 = c64[i][j][0], v1 = c64[i][j][1];
            float v2 = c64[i][j][2], v3 = c64[i][j][3];
            if (EPI == 1) {
                float* Out = (float*)OutV;
                float2 t0 = *(const float2*)(R + (size_t)r0 * N + cc);
                float2 t1 = *(const float2*)(R + (size_t)r1 * N + cc);
                *(float2*)(Out + (size_t)r0 * N + cc) = make_float2(v0 + t0.x, v1 + t0.y);
                *(float2*)(Out + (size_t)r1 * N + cc) = make_float2(v2 + t1.x, v3 + t1.y);
            } else {
                __half* Out = (__half*)OutV;
                v0 = fmaxf(v0, 0.f); v1 = fmaxf(v1, 0.f);
                v2 = fmaxf(v2, 0.f); v3 = fmaxf(v3, 0.f);
                *(uint32_t*)(Out + (size_t)r0 * N + cc) = packh2(v0 * v0, v1 * v1);
                *(uint32_t*)(Out + (size_t)r1 * N + cc) = packh2(v2 * v2, v3 * v3);
            }
        }
    }
}

// ============ QKV GEMM on the gemm64 path; RoPE via smem exchange epilogue ============
#define PSTRIDE 68
__global__ __launch_bounds__(256, 3) void qkv_gemm64(const __half* __restrict__ A,
                                                     const __half* __restrict__ wqt,
                                                     const __half* __restrict__ wkt,
                                                     const __half* __restrict__ wvt,
                                                     const float* __restrict__ cs,
                                                     const float* __restrict__ sn,
                                                     __half* __restrict__ q,
                                                     __half* __restrict__ k,
                                                     __half* __restrict__ v) {
    extern __shared__ char sm[];
    const int mat = blockIdx.x / 12;
    const int bn = (blockIdx.x % 12) * 64;       // one full head
    const int bm = blockIdx.y * 128;
    const __half* Wt = (mat == 0) ? wqt : (mat == 1) ? wkt : wvt;
    __half* Out = (mat == 0) ? q : (mat == 1) ? k : v;
    const float sc = (mat == 0) ? 0.125f * LOG2E : 1.0f;

    float c64[2][4][4];
    gemm_mainloop64(A, Wt, CD, bm, bn, sm, c64);

    const int tid = threadIdx.x;
    const int warp = tid >> 5, lane = tid & 31;
    const int wy = warp >> 1, wx = warp & 1;
    const int gid = lane >> 2, tig = lane & 3;

    if (mat == 2) {  // v: direct store
        #pragma unroll
        for (int i = 0; i < 2; i++) {
            const int r0 = bm + wy * 32 + i * 16 + gid;
            const int r1 = r0 + 8;
            #pragma unroll
            for (int j = 0; j < 4; j++) {
                const int cc = bn + wx * 32 + j * 8 + 2 * tig;
                *(uint32_t*)(Out + (size_t)r0 * CD + cc) = packh2(c64[i][j][0], c64[i][j][1]);
                *(uint32_t*)(Out + (size_t)r1 * CD + cc) = packh2(c64[i][j][2], c64[i][j][3]);
            }
        }
        return;
    }

    // q/k: exchange accumulators through smem (stage buffers are dead now)
    __syncthreads();
    float* P = (float*)sm;                        // [128][PSTRIDE]
    #pragma unroll
    for (int i = 0; i < 2; i++) {
        const int lr0 = wy * 32 + i * 16 + gid;
        const int lr1 = lr0 + 8;
        #pragma unroll
        for (int j = 0; j < 4; j++) {
            const int col = wx * 32 + j * 8 + 2 * tig;
            P[lr0 * PSTRIDE + col]     = c64[i][j][0];
            P[lr0 * PSTRIDE + col + 1] = c64[i][j][1];
            P[lr1 * PSTRIDE + col]     = c64[i][j][2];
            P[lr1 * PSTRIDE + col + 1] = c64[i][j][3];
        }
    }
    __syncthreads();

    #pragma unroll
    for (int i = 0; i < 2; i++) {
        const int lr0 = wy * 32 + i * 16 + gid;
        const int lr1 = lr0 + 8;
        const int r0 = bm + lr0, r1 = bm + lr1;
        const int t0 = r0 & (TT - 1), t1 = r1 & (TT - 1);
        #pragma unroll
        for (int j = 0; j < 4; j++) {
            const int col = wx * 32 + j * 8 + 2 * tig;   // 0..63
            const int d = col & 31;
            float2 cA = *(const float2*)(cs + t0 * DD2 + d);
            float2 sA = *(const float2*)(sn + t0 * DD2 + d);
            float2 cB = *(const float2*)(cs + t1 * DD2 + d);
            float2 sB = *(const float2*)(sn + t1 * DD2 + d);
            float o0a, o0b, o1a, o1b;
            if (col < 32) {   // out = x1*cos + x2*sin
                o0a = P[lr0 * PSTRIDE + col] * cA.x     + P[lr0 * PSTRIDE + col + 32] * sA.x;
                o0b = P[lr0 * PSTRIDE + col + 1] * cA.y + P[lr0 * PSTRIDE + col + 33] * sA.y;
                o1a = P[lr1 * PSTRIDE + col] * cB.x     + P[lr1 * PSTRIDE + col + 32] * sB.x;
                o1b = P[lr1 * PSTRIDE + col + 1] * cB.y + P[lr1 * PSTRIDE + col + 33] * sB.y;
            } else {          // out = -x1*sin + x2*cos
                o0a = -P[lr0 * PSTRIDE + col - 32] * sA.x + P[lr0 * PSTRIDE + col] * cA.x;
                o0b = -P[lr0 * PSTRIDE + col - 31] * sA.y + P[lr0 * PSTRIDE + col + 1] * cA.y;
                o1a = -P[lr1 * PSTRIDE + col - 32] * sB.x + P[lr1 * PSTRIDE + col] * cB.x;
                o1b = -P[lr1 * PSTRIDE + col - 31] * sB.y + P[lr1 * PSTRIDE + col + 1] * cB.y;
            }
            *(uint32_t*)(Out + (size_t)r0 * CD + bn + col) = packh2(sc * o0a, sc * o0b);
            *(uint32_t*)(Out + (size_t)r1 * CD + bn + col) = packh2(sc * o1a, sc * o1b);
        }
    }
}

// ---------------- RMSNorm: f32 in, half out (vectorized) ----------------
__global__ __launch_bounds__(256) void rmsnorm_kernel(const float* __restrict__ x,
                                                      const float* __restrict__ g,
                                                      __half* __restrict__ out) {
    const int row = blockIdx.x;
    const int i = threadIdx.x;
    const float* xr = x + (size_t)row * CD;
    float4 v = make_float4(0.f, 0.f, 0.f, 0.f);
    if (i < 192) v = *(const float4*)(xr + i * 4);
    float ss = v.x * v.x + v.y * v.y + v.z * v.z + v.w * v.w;
    #pragma unroll
    for (int o = 16; o; o >>= 1) ss += __shfl_xor_sync(0xffffffffu, ss, o);
    __shared__ float red[8];
    if ((i & 31) == 0) red[i >> 5] = ss;
    __syncthreads();
    float tot = 0.f;
    #pragma unroll
    for (int p = 0; p < 8; p++) tot += red[p];
    const float rinv = rsqrtf(tot / (float)CD + kEPS);
    if (i < 192) {
        float4 gv = *(const float4*)(g + i * 4);
        uint2 o2;
        o2.x = packh2(gv.x * v.x * rinv, gv.y * v.y * rinv);
        o2.y = packh2(gv.z * v.z * rinv, gv.w * v.w * rinv);
        *(uint2*)(out + (size_t)row * CD + i * 4) = o2;
    }
}

// ---------------- fp16 Flash Attention: 128-key stages, warp skip, big-first ----------------
#define KSTG_B (128 * ROWB)
#define STAGEKV_B (2 * KSTG_B)
#define ATTN_SMEM (128 * ROWB + 2 * STAGEKV_B)  // 92160 B
__global__ __launch_bounds__(256, 2) void attn_f16(const __half* __restrict__ q,
                                                   const __half* __restrict__ k,
                                                   const __half* __restrict__ v,
                                                   __half* __restrict__ y) {
    extern __shared__ char asmc[];
    __half* uQ = (__half*)asmc;

    const int h = blockIdx.x % HH, b = blockIdx.x / HH;
    const int qtb = (int)gridDim.y - 1 - (int)blockIdx.y;
    const int tid = threadIdx.x, warp = tid >> 5, lane = tid & 31;
    const int gid = lane >> 2, tig = lane & 3;
    const int qs = qtb * 128;
    const size_t bh = (size_t)b * TT * CD + (size_t)h * HDIM;

    const uint32_t sQ = smem_u32(uQ);
    const uint32_t kvBase[2] = { sQ + 128 * ROWB, sQ + 128 * ROWB + STAGEKV_B };
    const int l7 = lane & 7;
    const uint32_t aLd = (uint32_t)(((lane >> 3) & 1) * 8 + l7) * ROWB + (lane >> 4) * 16;
    const uint32_t bLd = (uint32_t)(((lane >> 4) & 1) * 8 + l7) * ROWB + ((lane >> 3) & 1) * 16;
    const uint32_t vLd = (uint32_t)(((lane >> 3) & 1) * 8 + l7) * ROWB + ((lane >> 4) & 1) * 16;

    for (int i = tid; i < 128 * 8; i += 256) {
        const int r = i >> 3, g = i & 7;
        *(uint4*)((char*)uQ + r * ROWB + g * 16) =
            *(const uint4*)(q + bh + (size_t)(qs + r) * CD + g * 8);
    }
    __syncthreads();

    uint32_t qf[4][4];
    #pragma unroll
    for (int kb = 0; kb < 4; kb++)
        ldsm4(qf[kb], sQ + (uint32_t)(warp * 16) * ROWB + aLd + kb * 32);

    float m[2] = {-1e30f, -1e30f}, l[2] = {0.f, 0.f};
    float o[8][4];
    #pragma unroll
    for (int j = 0; j < 8; j++)
        #pragma unroll
        for (int t = 0; t < 4; t++) o[j][t] = 0.f;

    const int qrow0 = qs + warp * 16;
    const int nst = qtb + 1;

    const int srow = tid >> 1, sg = (tid & 1) * 4;

    #pragma unroll
    for (int p = 0; p < 4; p++) {
        cp16(kvBase[0] + srow * ROWB + (sg + p) * 16,
             k + bh + (size_t)srow * CD + (sg + p) * 8);
        cp16(kvBase[0] + KSTG_B + srow * ROWB + (sg + p) * 16,
             v + bh + (size_t)srow * CD + (sg + p) * 8);
    }
    CP_COMMIT();

    for (int st = 0; st < nst; st++) {
        CP_WAIT0();
        __syncthreads();
        if (st + 1 < nst) {
            const uint32_t dstb = kvBase[(st + 1) & 1];
            const int ks1 = (st + 1) * 128 + srow;
            #pragma unroll
            for (int p = 0; p < 4; p++) {
                cp16(dstb + srow * ROWB + (sg + p) * 16,
                     k + bh + (size_t)ks1 * CD + (sg + p) * 8);
                cp16(dstb + KSTG_B + srow * ROWB + (sg + p) * 16,
                     v + bh + (size_t)ks1 * CD + (sg + p) * 8);
            }
        }
        CP_COMMIT();

        #pragma unroll
        for (int sub = 0; sub < 2; sub++) {
            const int ks = st * 128 + sub * 64;
            if (ks > qrow0 + 15) continue;
            const uint32_t sK = kvBase[st & 1] + (uint32_t)(sub * 64) * ROWB;
            const uint32_t sV = kvBase[st & 1] + KSTG_B + (uint32_t)(sub * 64) * ROWB;

            float sf[8][4];
            #pragma unroll
            for (int j = 0; j < 8; j++)
                #pragma unroll
                for (int t = 0; t < 4; t++) sf[j][t] = 0.f;
            #pragma unroll
            for (int kb = 0; kb < 4; kb++) {
                uint32_t bf[4][4];
                #pragma unroll
                for (int p = 0; p < 4; p++)
                    ldsm4(bf[p], sK + (uint32_t)(p * 16) * ROWB + bLd + kb * 32);
                #pragma unroll
                for (int j = 0; j < 8; j++)
                    mma_f16(sf[j], qf[kb], &bf[j >> 1][(j & 1) * 2]);
            }

            if (ks + 63 > qrow0) {
                const int qr0 = qrow0 + gid, qr1 = qr0 + 8;
                #pragma unroll
                for (int j = 0; j < 8; j++) {
                    const int kc = ks + j * 8 + 2 * tig;
                    if (kc > qr0)     sf[j][0] = -1e30f;
                    if (kc + 1 > qr0) sf[j][1] = -1e30f;
                    if (kc > qr1)     sf[j][2] = -1e30f;
                    if (kc + 1 > qr1) sf[j][3] = -1e30f;
                }
            }

            #pragma unroll
            for (int r = 0; r < 2; r++) {
                float mx = -1e30f;
                #pragma unroll
                for (int j = 0; j < 8; j++)
                    mx = fmaxf(mx, fmaxf(sf[j][2 * r], sf[j][2 * r + 1]));
                mx = fmaxf(mx, __shfl_xor_sync(0xffffffffu, mx, 1));
                mx = fmaxf(mx, __shfl_xor_sync(0xffffffffu, mx, 2));
                const float mnew = fmaxf(m[r], mx);
                const float alpha = exp2f(m[r] - mnew);
                float rs = 0.f;
                #pragma unroll
                for (int j = 0; j < 8; j++) {
                    float p0 = exp2f(sf[j][2 * r] - mnew);
                    float p1 = exp2f(sf[j][2 * r + 1] - mnew);
                    sf[j][2 * r] = p0; sf[j][2 * r + 1] = p1;
                    rs += p0 + p1;
                }
                rs += __shfl_xor_sync(0xffffffffu, rs, 1);
                rs += __shfl_xor_sync(0xffffffffu, rs, 2);
                l[r] = l[r] * alpha + rs;
                m[r] = mnew;
                #pragma unroll
                for (int j = 0; j < 8; j++) { o[j][2 * r] *= alpha; o[j][2 * r + 1] *= alpha; }
            }

            #pragma unroll
            for (int kb = 0; kb < 4; kb++) {
                uint32_t pa[4];
                pa[0] = packh2(sf[2 * kb][0],     sf[2 * kb][1]);
                pa[1] = packh2(sf[2 * kb][2],     sf[2 * kb][3]);
                pa[2] = packh2(sf[2 * kb + 1][0], sf[2 * kb + 1][1]);
                pa[3] = packh2(sf[2 * kb + 1][2], sf[2 * kb + 1][3]);
                uint32_t vf[4][4];
                #pragma unroll
                for (int p = 0; p < 4; p++)
                    ldsm4t(vf[p], sV + (uint32_t)(kb * 16) * ROWB + vLd + p * 32);
                #pragma unroll
                for (int j = 0; j < 8; j++)
                    mma_f16(o[j], pa, &vf[j >> 1][(j & 1) * 2]);
            }
        }
    }

    const float inv0 = 1.f / l[0], inv1 = 1.f / l[1];
    const int qa0 = qs + warp * 16 + gid, qa1 = qa0 + 8;
    #pragma unroll
    for (int j = 0; j < 8; j++) {
        const int cc = j * 8 + 2 * tig;
        *(uint32_t*)(y + bh + (size_t)qa0 * CD + cc) = packh2(o[j][0] * inv0, o[j][1] * inv0);
        *(uint32_t*)(y + bh + (size_t)qa1 * CD + cc) = packh2(o[j][2] * inv1, o[j][3] * inv1);
    }
}

// ---------------- launch ----------------
extern "C" void kernel_launch(void* const* d_in, const int* in_sizes, int n_in,
                              void* d_out, int out_size) {
    const float* x   = (const float*)d_in[0];
    const float* cs  = (const float*)d_in[1];
    const float* sn  = (const float*)d_in[2];
    const float* wq  = (const float*)d_in[3];
    const float* wk  = (const float*)d_in[4];
    const float* wv  = (const float*)d_in[5];
    const float* wo  = (const float*)d_in[6];
    const float* wfc = (const float*)d_in[7];
    const float* wpr = (const float*)d_in[8];
    const float* g1  = (const float*)d_in[9];
    const float* g2  = (const float*)d_in[10];
    float* out = (float*)d_out;

    __half *h, *q, *k, *v, *y, *ff;
    __half *wqt, *wkt, *wvt, *wot, *wfct, *wprt;
    float *x2;
    cudaGetSymbolAddress((void**)&h,  g_h);
    cudaGetSymbolAddress((void**)&q,  g_q);
    cudaGetSymbolAddress((void**)&k,  g_k);
    cudaGetSymbolAddress((void**)&v,  g_v);
    cudaGetSymbolAddress((void**)&y,  g_y);
    cudaGetSymbolAddress((void**)&ff, g_ff);
    cudaGetSymbolAddress((void**)&x2, g_x2);
    cudaGetSymbolAddress((void**)&wqt,  g_wqt);
    cudaGetSymbolAddress((void**)&wkt,  g_wkt);
    cudaGetSymbolAddress((void**)&wvt,  g_wvt);
    cudaGetSymbolAddress((void**)&wot,  g_wot);
    cudaGetSymbolAddress((void**)&wfct, g_wfct);
    cudaGetSymbolAddress((void**)&wprt, g_wprt);

    cudaFuncSetAttribute((const void*)attn_f16,
                         cudaFuncAttributeMaxDynamicSharedMemorySize, ATTN_SMEM);
    cudaFuncSetAttribute((const void*)qkv_gemm64,
                         cudaFuncAttributeMaxDynamicSharedMemorySize, GEMM64_SMEM);
    cudaFuncSetAttribute((const void*)gemm64_f16<1>,
                         cudaFuncAttributeMaxDynamicSharedMemorySize, GEMM64_SMEM);
    cudaFuncSetAttribute((const void*)gemm64_f16<2>,
                         cudaFuncAttributeMaxDynamicSharedMemorySize, GEMM64_SMEM);

    // 0. batched transpose+convert
    transp_all<<<dim3(96, 24, 6), 256>>>(wq, wk, wv, wo, wfc, wpr,
                                         wqt, wkt, wvt, wot, wfct, wprt);

    // 1. h = rmsnorm(x, g1)
    rmsnorm_kernel<<<NROWS, 256>>>(x, g1, h);

    // 2+3. q,k,v on the swizzled 3-CTA/SM path; RoPE via smem-exchange epilogue
    qkv_gemm64<<<dim3(36, 32), 256, GEMM64_SMEM>>>(h, wqt, wkt, wvt, cs, sn, q, k, v);

    // 4. attention -> y
    attn_f16<<<dim3(HH * BB, TT / 128), 256, ATTN_SMEM>>>(q, k, v, y);

    // 5. x2 = x + y @ wo
    gemm64_f16<1><<<dim3(CD / 64, NROWS / 128), 256, GEMM64_SMEM>>>(y, wot, x, x2, CD, CD);

    // 6. h = rmsnorm(x2, g2)
    rmsnorm_kernel<<<NROWS, 256>>>(x2, g2, h);

    // 7. ff = relu(h @ wfc)^2
    gemm64_f16<2><<<dim3(FFD / 64, NROWS / 128), 256, GEMM64_SMEM>>>(h, wfct, nullptr, ff, FFD, CD);

    // 8. out = x2 + ff @ wpr
    gemm64_f16<1><<<dim3(CD / 64, NROWS / 128), 256, GEMM64_SMEM>>>(ff, wprt, x2, out, CD, FFD);
}

// round 17
// speedup vs baseline: 1.0149x; 1.0149x over previous
#include <cuda_runtime.h>
#include <cuda_fp16.h>
#include <math.h>
#include <stdint.h>

// Problem constants
#define BB 2
#define TT 2048
#define CD 768
#define HH 12
#define HDIM 64
#define DD2 32
#define FFD 3072
#define NROWS (BB*TT)          // 4096
static __device__ __constant__ float kEPS = 1e-5f;
#define LOG2E 1.44269504088896340736f

// ---------------- scratch ----------------
__device__ __half g_h [NROWS*CD];
__device__ __half g_q [NROWS*CD];
__device__ __half g_k [NROWS*CD];
__device__ __half g_v [NROWS*CD];
__device__ __half g_y [NROWS*CD];
__device__ __half g_ff[NROWS*FFD];
__device__ float  g_x2[NROWS*CD];
__device__ __half g_wqt [CD*CD];
__device__ __half g_wkt [CD*CD];
__device__ __half g_wvt [CD*CD];
__device__ __half g_wot [CD*CD];
__device__ __half g_wfct[FFD*CD];
__device__ __half g_wprt[CD*FFD];

// ---------------- helpers ----------------
__device__ __forceinline__ void mma_f16(float* c, const uint32_t* a, const uint32_t* b) {
    asm volatile(
        "mma.sync.aligned.m16n8k16.row.col.f32.f16.f16.f32 "
        "{%0,%1,%2,%3}, {%4,%5,%6,%7}, {%8,%9}, {%0,%1,%2,%3};"
        : "+f"(c[0]), "+f"(c[1]), "+f"(c[2]), "+f"(c[3])
        : "r"(a[0]), "r"(a[1]), "r"(a[2]), "r"(a[3]), "r"(b[0]), "r"(b[1]));
}
__device__ __forceinline__ void ldsm4(uint32_t* r, uint32_t addr) {
    asm volatile("ldmatrix.sync.aligned.m8n8.x4.shared.b16 {%0,%1,%2,%3}, [%4];"
                 : "=r"(r[0]), "=r"(r[1]), "=r"(r[2]), "=r"(r[3]) : "r"(addr));
}
__device__ __forceinline__ void ldsm4t(uint32_t* r, uint32_t addr) {
    asm volatile("ldmatrix.sync.aligned.m8n8.x4.trans.shared.b16 {%0,%1,%2,%3}, [%4];"
                 : "=r"(r[0]), "=r"(r[1]), "=r"(r[2]), "=r"(r[3]) : "r"(addr));
}
__device__ __forceinline__ uint32_t smem_u32(const void* p) {
    uint32_t a;
    asm("{ .reg .u64 t; cvta.to.shared.u64 t, %1; cvt.u32.u64 %0, t; }" : "=r"(a) : "l"(p));
    return a;
}
__device__ __forceinline__ void cp16(uint32_t dst, const void* src) {
    asm volatile("cp.async.cg.shared.global [%0], [%1], 16;" :: "r"(dst), "l"(src));
}
#define CP_COMMIT() asm volatile("cp.async.commit_group;" ::: "memory")
#define CP_WAIT1()  asm volatile("cp.async.wait_group 1;" ::: "memory")
#define CP_WAIT0()  asm volatile("cp.async.wait_group 0;" ::: "memory")
__device__ __forceinline__ uint32_t packh2(float a, float b) {
    __half2 h = __floats2half2_rn(a, b);
    return *(uint32_t*)&h;
}

// ---------------- fused prologue: weight transposes (z<6) + rmsnorm1 (z==6) ----------------
__global__ __launch_bounds__(256) void prolog_all(
    const float* __restrict__ wq, const float* __restrict__ wk,
    const float* __restrict__ wv, const float* __restrict__ wo,
    const float* __restrict__ wfc, const float* __restrict__ wpr,
    __half* __restrict__ wqt, __half* __restrict__ wkt,
    __half* __restrict__ wvt, __half* __restrict__ wot,
    __half* __restrict__ wfct, __half* __restrict__ wprt,
    const float* __restrict__ x, const float* __restrict__ g1,
    __half* __restrict__ hout) {
    const int z = blockIdx.z, a = blockIdx.x, b = blockIdx.y;
    if (z == 6) {
        // rmsnorm: 2 rows per block
        const int idx = b * 96 + a;
        const int i = threadIdx.x;
        #pragma unroll
        for (int rr = 0; rr < 2; rr++) {
            const int row = idx * 2 + rr;
            if (row >= NROWS) break;
            const float* xr = x + (size_t)row * CD;
            float4 v = make_float4(0.f, 0.f, 0.f, 0.f);
            if (i < 192) v = *(const float4*)(xr + i * 4);
            float ss = v.x * v.x + v.y * v.y + v.z * v.z + v.w * v.w;
            #pragma unroll
            for (int o = 16; o; o >>= 1) ss += __shfl_xor_sync(0xffffffffu, ss, o);
            __shared__ float red[8];
            if ((i & 31) == 0) red[i >> 5] = ss;
            __syncthreads();
            float tot = 0.f;
            #pragma unroll
            for (int p = 0; p < 8; p++) tot += red[p];
            const float rinv = rsqrtf(tot / (float)CD + kEPS);
            if (i < 192) {
                float4 gv = *(const float4*)(g1 + i * 4);
                uint2 o2;
                o2.x = packh2(gv.x * v.x * rinv, gv.y * v.y * rinv);
                o2.y = packh2(gv.z * v.z * rinv, gv.w * v.w * rinv);
                *(uint2*)(hout + (size_t)row * CD + i * 4) = o2;
            }
            __syncthreads();
        }
        return;
    }
    const float* src; __half* dst; int R, C, c0, r0;
    if (z < 4) {
        if (a >= 24) return;
        src = (z == 0) ? wq : (z == 1) ? wk : (z == 2) ? wv : wo;
        dst = (z == 0) ? wqt : (z == 1) ? wkt : (z == 2) ? wvt : wot;
        R = CD; C = CD; c0 = a * 32; r0 = b * 32;
    } else if (z == 4) {
        src = wfc; dst = wfct; R = CD; C = FFD; c0 = a * 32; r0 = b * 32;
    } else {
        src = wpr; dst = wprt; R = FFD; C = CD; c0 = b * 32; r0 = a * 32;
    }
    __shared__ float t[32][33];
    const int tx = threadIdx.x & 31, ty = threadIdx.x >> 5;
    #pragma unroll
    for (int p = 0; p < 4; p++)
        t[ty + p * 8][tx] = src[(size_t)(r0 + ty + p * 8) * C + c0 + tx];
    __syncthreads();
    #pragma unroll
    for (int p = 0; p < 4; p++)
        dst[(size_t)(c0 + ty + p * 8) * R + r0 + tx] = __float2half_rn(t[tx][ty + p * 8]);
}

// SMEM geometry (padded path: BN=128 qkv + attention)
#define STH 72
#define ROWB 144
#define A_ST_B (128 * ROWB)             // 18432
#define STAGE_B (2 * A_ST_B)            // 36864
#define NSTAGE 3
#define GEMM_SMEM (NSTAGE * STAGE_B)    // 110592
// swizzled BN=64 path: exact 128B rows
#define A64_B (128 * 128)               // 16384
#define B64_B (64 * 128)                // 8192
#define STAGE64_B (A64_B + B64_B)       // 24576
#define GEMM64_SMEM (NSTAGE * STAGE64_B) // 73728

// ============ fp16 GEMM core BN=128 (padded rows): 256 thr, warp 32x64 ============
struct GemmAcc { float c[2][8][4]; };

__device__ __forceinline__ void gemm_mainloop(const __half* __restrict__ A,
                                              const __half* __restrict__ Wt,
                                              int K, int bm, int bn, char* sm,
                                              GemmAcc& G) {
    const int tid = threadIdx.x;
    const int warp = tid >> 5, lane = tid & 31;
    const int wy = warp >> 1, wx = warp & 1;

    #pragma unroll
    for (int i = 0; i < 2; i++)
        #pragma unroll
        for (int j = 0; j < 8; j++)
            #pragma unroll
            for (int t = 0; t < 4; t++) G.c[i][j][t] = 0.f;

    const int NC = K >> 6;
    const uint32_t sbase = smem_u32(sm);

    const int row = tid >> 1, gb = (tid & 1) * 4;
    const __half* Ab = A + (size_t)(bm + row) * K + gb * 8;
    const __half* Bb = Wt + (size_t)(bn + row) * K + gb * 8;
    const uint32_t aOff = (uint32_t)(row * ROWB + gb * 16);
    const uint32_t bOff = (uint32_t)(A_ST_B + row * ROWB + gb * 16);

    const int l7 = lane & 7;
    const uint32_t aLd = (uint32_t)(wy * 32 + ((lane >> 3) & 1) * 8 + l7) * ROWB + (lane >> 4) * 16;
    const uint32_t bLd = (uint32_t)(wx * 64 + ((lane >> 4) & 1) * 8 + l7) * ROWB + ((lane >> 3) & 1) * 16;

    #pragma unroll
    for (int s = 0; s < 2; s++) {
        const uint32_t st = sbase + s * STAGE_B;
        #pragma unroll
        for (int p = 0; p < 4; p++) cp16(st + aOff + p * 16, Ab + s * 64 + p * 8);
        #pragma unroll
        for (int p = 0; p < 4; p++) cp16(st + bOff + p * 16, Bb + s * 64 + p * 8);
        CP_COMMIT();
    }

    int s = 0;
    for (int c = 0; c < NC; c++) {
        CP_WAIT1();
        __syncthreads();
        if (c + 2 < NC) {
            const int s2 = (s + 2 >= NSTAGE) ? s + 2 - NSTAGE : s + 2;
            const uint32_t st = sbase + s2 * STAGE_B;
            #pragma unroll
            for (int p = 0; p < 4; p++) cp16(st + aOff + p * 16, Ab + (c + 2) * 64 + p * 8);
            #pragma unroll
            for (int p = 0; p < 4; p++) cp16(st + bOff + p * 16, Bb + (c + 2) * 64 + p * 8);
        }
        CP_COMMIT();

        const uint32_t aBase = sbase + s * STAGE_B + aLd;
        const uint32_t bBase = sbase + s * STAGE_B + A_ST_B + bLd;
        #pragma unroll
        for (int ks = 0; ks < 4; ks++) {
            uint32_t af[2][4], bf[4][4];
            ldsm4(af[0], aBase + ks * 32);
            ldsm4(af[1], aBase + 16 * ROWB + ks * 32);
            #pragma unroll
            for (int p = 0; p < 4; p++) ldsm4(bf[p], bBase + p * 16 * ROWB + ks * 32);
            #pragma unroll
            for (int i = 0; i < 2; i++)
                #pragma unroll
                for (int j = 0; j < 8; j++)
                    mma_f16(G.c[i][j], af[i], &bf[j >> 1][(j & 1) * 2]);
        }
        s = (s + 1 >= NSTAGE) ? 0 : s + 1;
    }
}

// ============ fp16 GEMM core BN=64, XOR-swizzled, 3 CTAs/SM (wo/fc/pr) ============
__device__ __forceinline__ void gemm_mainloop64(const __half* __restrict__ A,
                                                const __half* __restrict__ Wt,
                                                int K, int bm, int bn, char* sm,
                                                float c64[2][4][4]) {
    const int tid = threadIdx.x;
    const int warp = tid >> 5, lane = tid & 31;
    const int wy = warp >> 1, wx = warp & 1;

    #pragma unroll
    for (int i = 0; i < 2; i++)
        #pragma unroll
        for (int j = 0; j < 4; j++)
            #pragma unroll
            for (int t = 0; t < 4; t++) c64[i][j][t] = 0.f;

    const int NC = K >> 6;
    const uint32_t sbase = smem_u32(sm);

    const int rowA = tid >> 1, gA = (tid & 1) * 4;
    const __half* Ab = A + (size_t)(bm + rowA) * K + gA * 8;
    const uint32_t aRow = (uint32_t)rowA * 128;
    const int aMsk = rowA & 7;
    const int rowB = tid >> 2, gB = (tid & 3) * 2;
    const __half* Bb = Wt + (size_t)(bn + rowB) * K + gB * 8;
    const uint32_t bRow = (uint32_t)(A64_B + rowB * 128);
    const int bMsk = rowB & 7;

    const int l7 = lane & 7;
    const int rA = wy * 32 + ((lane >> 3) & 1) * 8 + l7;
    const int cA = lane >> 4;
    const int mA = rA & 7;
    const int rB = wx * 32 + ((lane >> 4) & 1) * 8 + l7;
    const int cB = (lane >> 3) & 1;
    const int mB = rB & 7;

    #pragma unroll
    for (int s = 0; s < 2; s++) {
        const uint32_t st = sbase + s * STAGE64_B;
        #pragma unroll
        for (int p = 0; p < 4; p++)
            cp16(st + aRow + (((gA + p) ^ aMsk) * 16), Ab + s * 64 + p * 8);
        #pragma unroll
        for (int p = 0; p < 2; p++)
            cp16(st + bRow + (((gB + p) ^ bMsk) * 16), Bb + s * 64 + p * 8);
        CP_COMMIT();
    }

    int s = 0;
    for (int c = 0; c < NC; c++) {
        CP_WAIT1();
        __syncthreads();
        if (c + 2 < NC) {
            const int s2 = (s + 2 >= NSTAGE) ? s + 2 - NSTAGE : s + 2;
            const uint32_t st = sbase + s2 * STAGE64_B;
            #pragma unroll
            for (int p = 0; p < 4; p++)
                cp16(st + aRow + (((gA + p) ^ aMsk) * 16), Ab + (c + 2) * 64 + p * 8);
            #pragma unroll
            for (int p = 0; p < 2; p++)
                cp16(st + bRow + (((gB + p) ^ bMsk) * 16), Bb + (c + 2) * 64 + p * 8);
        }
        CP_COMMIT();

        const uint32_t stA = sbase + s * STAGE64_B;
        const uint32_t stB = stA + A64_B;
        #pragma unroll
        for (int ks = 0; ks < 4; ks++) {
            uint32_t af[2][4], bf[2][4];
            const uint32_t ca = (uint32_t)(((cA + 2 * ks) ^ mA) * 16);
            ldsm4(af[0], stA + (uint32_t)rA * 128 + ca);
            ldsm4(af[1], stA + (uint32_t)(rA + 16) * 128 + ca);
            const uint32_t cb = (uint32_t)(((cB + 2 * ks) ^ mB) * 16);
            ldsm4(bf[0], stB + (uint32_t)rB * 128 + cb);
            ldsm4(bf[1], stB + (uint32_t)(rB + 16) * 128 + cb);
            #pragma unroll
            for (int i = 0; i < 2; i++)
                #pragma unroll
                for (int j = 0; j < 4; j++)
                    mma_f16(c64[i][j], af[i], &bf[j >> 1][(j & 1) * 2]);
        }
        s = (s + 1 >= NSTAGE) ? 0 : s + 1;
    }
}

// ============ GEMM kernels (wo/fc/pr) ============
template <int EPI>
__global__ __launch_bounds__(256, 3) void gemm64_f16(const __half* __restrict__ A,
                                                     const __half* __restrict__ Wt,
                                                     const float* __restrict__ R,
                                                     void* __restrict__ OutV,
                                                     int N, int K) {
    extern __shared__ char sm[];
    const int bm = blockIdx.y * 128, bn = blockIdx.x * 64;
    float c64[2][4][4];
    gemm_mainloop64(A, Wt, K, bm, bn, sm, c64);

    const int tid = threadIdx.x;
    const int warp = tid >> 5, lane = tid & 31;
    const int wy = warp >> 1, wx = warp & 1;
    const int gid = lane >> 2, tig = lane & 3;

    #pragma unroll
    for (int i = 0; i < 2; i++) {
        const int r0 = bm + wy * 32 + i * 16 + gid;
        const int r1 = r0 + 8;
        #pragma unroll
        for (int j = 0; j < 4; j++) {
            const int cc = bn + wx * 32 + j * 8 + 2 * tig;
            float v0 = c64[i][j][0], v1 = c64[i][j][1];
            float v2 = c64[i][j][2], v3 = c64[i][j][3];
            if (EPI == 1) {
                float* Out = (float*)OutV;
                float2 t0 = *(const float2*)(R + (size_t)r0 * N + cc);
                float2 t1 = *(const float2*)(R + (size_t)r1 * N + cc);
                *(float2*)(Out + (size_t)r0 * N + cc) = make_float2(v0 + t0.x, v1 + t0.y);
                *(float2*)(Out + (size_t)r1 * N + cc) = make_float2(v2 + t1.x, v3 + t1.y);
            } else {
                __half* Out = (__half*)OutV;
                v0 = fmaxf(v0, 0.f); v1 = fmaxf(v1, 0.f);
                v2 = fmaxf(v2, 0.f); v3 = fmaxf(v3, 0.f);
                *(uint32_t*)(Out + (size_t)r0 * N + cc) = packh2(v0 * v0, v1 * v1);
                *(uint32_t*)(Out + (size_t)r1 * N + cc) = packh2(v2 * v2, v3 * v3);
            }
        }
    }
}

// ============ fused QKV GEMM BN=128 + RoPE (q pre-scaled by 0.125*log2e) ============
__global__ __launch_bounds__(256, 2) void qkv_gemm(const __half* __restrict__ A,
                                                   const __half* __restrict__ wqt,
                                                   const __half* __restrict__ wkt,
                                                   const __half* __restrict__ wvt,
                                                   const float* __restrict__ cs,
                                                   const float* __restrict__ sn,
                                                   __half* __restrict__ q,
                                                   __half* __restrict__ k,
                                                   __half* __restrict__ v) {
    extern __shared__ char sm[];
    const int mat = blockIdx.x / 6;
    const int bn = (blockIdx.x % 6) * 128;
    const int bm = blockIdx.y * 128;
    const __half* Wt = (mat == 0) ? wqt : (mat == 1) ? wkt : wvt;
    __half* Out = (mat == 0) ? q : (mat == 1) ? k : v;
    const float sc = (mat == 0) ? 0.125f * LOG2E : 1.0f;

    GemmAcc G;
    gemm_mainloop(A, Wt, CD, bm, bn, sm, G);

    const int tid = threadIdx.x;
    const int warp = tid >> 5, lane = tid & 31;
    const int wy = warp >> 1, wx = warp & 1;
    const int gid = lane >> 2, tig = lane & 3;

    if (mat == 2) {
        #pragma unroll
        for (int i = 0; i < 2; i++) {
            const int r0 = bm + wy * 32 + i * 16 + gid;
            const int r1 = r0 + 8;
            #pragma unroll
            for (int j = 0; j < 8; j++) {
                const int cc = bn + wx * 64 + j * 8 + 2 * tig;
                *(uint32_t*)(Out + (size_t)r0 * CD + cc) = packh2(G.c[i][j][0], G.c[i][j][1]);
                *(uint32_t*)(Out + (size_t)r1 * CD + cc) = packh2(G.c[i][j][2], G.c[i][j][3]);
            }
        }
    } else {
        #pragma unroll
        for (int i = 0; i < 2; i++) {
            const int r0 = bm + wy * 32 + i * 16 + gid;
            const int r1 = r0 + 8;
            const int t0 = r0 & (TT - 1), t1 = r1 & (TT - 1);
            #pragma unroll
            for (int j = 0; j < 4; j++) {
                const int d = j * 8 + 2 * tig;
                const int cc = bn + wx * 64 + j * 8 + 2 * tig;
                float2 c0 = *(const float2*)(cs + t0 * DD2 + d);
                float2 s0 = *(const float2*)(sn + t0 * DD2 + d);
                float2 c1 = *(const float2*)(cs + t1 * DD2 + d);
                float2 s1 = *(const float2*)(sn + t1 * DD2 + d);
                float x1a = G.c[i][j][0], x1b = G.c[i][j][1];
                float x2a = G.c[i][j + 4][0], x2b = G.c[i][j + 4][1];
                *(uint32_t*)(Out + (size_t)r0 * CD + cc) =
                    packh2(sc * (x1a * c0.x + x2a * s0.x), sc * (x1b * c0.y + x2b * s0.y));
                *(uint32_t*)(Out + (size_t)r0 * CD + cc + 32) =
                    packh2(sc * (-x1a * s0.x + x2a * c0.x), sc * (-x1b * s0.y + x2b * c0.y));
                float y1a = G.c[i][j][2], y1b = G.c[i][j][3];
                float y2a = G.c[i][j + 4][2], y2b = G.c[i][j + 4][3];
                *(uint32_t*)(Out + (size_t)r1 * CD + cc) =
                    packh2(sc * (y1a * c1.x + y2a * s1.x), sc * (y1b * c1.y + y2b * s1.y));
                *(uint32_t*)(Out + (size_t)r1 * CD + cc + 32) =
                    packh2(sc * (-y1a * s1.x + y2a * c1.x), sc * (-y1b * s1.y + y2b * c1.y));
            }
        }
    }
}

// ---------------- RMSNorm: f32 in, half out (vectorized; used for x2) ----------------
__global__ __launch_bounds__(256) void rmsnorm_kernel(const float* __restrict__ x,
                                                      const float* __restrict__ g,
                                                      __half* __restrict__ out) {
    const int row = blockIdx.x;
    const int i = threadIdx.x;
    const float* xr = x + (size_t)row * CD;
    float4 v = make_float4(0.f, 0.f, 0.f, 0.f);
    if (i < 192) v = *(const float4*)(xr + i * 4);
    float ss = v.x * v.x + v.y * v.y + v.z * v.z + v.w * v.w;
    #pragma unroll
    for (int o = 16; o; o >>= 1) ss += __shfl_xor_sync(0xffffffffu, ss, o);
    __shared__ float red[8];
    if ((i & 31) == 0) red[i >> 5] = ss;
    __syncthreads();
    float tot = 0.f;
    #pragma unroll
    for (int p = 0; p < 8; p++) tot += red[p];
    const float rinv = rsqrtf(tot / (float)CD + kEPS);
    if (i < 192) {
        float4 gv = *(const float4*)(g + i * 4);
        uint2 o2;
        o2.x = packh2(gv.x * v.x * rinv, gv.y * v.y * rinv);
        o2.y = packh2(gv.z * v.z * rinv, gv.w * v.w * rinv);
        *(uint2*)(out + (size_t)row * CD + i * 4) = o2;
    }
}

// ---------------- fp16 Flash Attention: 128-key stages, warp skip, big-first ----------------
#define KSTG_B (128 * ROWB)
#define STAGEKV_B (2 * KSTG_B)
#define ATTN_SMEM (128 * ROWB + 2 * STAGEKV_B)  // 92160 B
__global__ __launch_bounds__(256, 2) void attn_f16(const __half* __restrict__ q,
                                                   const __half* __restrict__ k,
                                                   const __half* __restrict__ v,
                                                   __half* __restrict__ y) {
    extern __shared__ char asmc[];
    __half* uQ = (__half*)asmc;

    const int h = blockIdx.x % HH, b = blockIdx.x / HH;
    const int qtb = (int)gridDim.y - 1 - (int)blockIdx.y;
    const int tid = threadIdx.x, warp = tid >> 5, lane = tid & 31;
    const int gid = lane >> 2, tig = lane & 3;
    const int qs = qtb * 128;
    const size_t bh = (size_t)b * TT * CD + (size_t)h * HDIM;

    const uint32_t sQ = smem_u32(uQ);
    const uint32_t kvBase[2] = { sQ + 128 * ROWB, sQ + 128 * ROWB + STAGEKV_B };
    const int l7 = lane & 7;
    const uint32_t aLd = (uint32_t)(((lane >> 3) & 1) * 8 + l7) * ROWB + (lane >> 4) * 16;
    const uint32_t bLd = (uint32_t)(((lane >> 4) & 1) * 8 + l7) * ROWB + ((lane >> 3) & 1) * 16;
    const uint32_t vLd = (uint32_t)(((lane >> 3) & 1) * 8 + l7) * ROWB + ((lane >> 4) & 1) * 16;

    for (int i = tid; i < 128 * 8; i += 256) {
        const int r = i >> 3, g = i & 7;
        *(uint4*)((char*)uQ + r * ROWB + g * 16) =
            *(const uint4*)(q + bh + (size_t)(qs + r) * CD + g * 8);
    }
    __syncthreads();

    uint32_t qf[4][4];
    #pragma unroll
    for (int kb = 0; kb < 4; kb++)
        ldsm4(qf[kb], sQ + (uint32_t)(warp * 16) * ROWB + aLd + kb * 32);

    float m[2] = {-1e30f, -1e30f}, l[2] = {0.f, 0.f};
    float o[8][4];
    #pragma unroll
    for (int j = 0; j < 8; j++)
        #pragma unroll
        for (int t = 0; t < 4; t++) o[j][t] = 0.f;

    const int qrow0 = qs + warp * 16;
    const int nst = qtb + 1;

    const int srow = tid >> 1, sg = (tid & 1) * 4;

    #pragma unroll
    for (int p = 0; p < 4; p++) {
        cp16(kvBase[0] + srow * ROWB + (sg + p) * 16,
             k + bh + (size_t)srow * CD + (sg + p) * 8);
        cp16(kvBase[0] + KSTG_B + srow * ROWB + (sg + p) * 16,
             v + bh + (size_t)srow * CD + (sg + p) * 8);
    }
    CP_COMMIT();

    for (int st = 0; st < nst; st++) {
        CP_WAIT0();
        __syncthreads();
        if (st + 1 < nst) {
            const uint32_t dstb = kvBase[(st + 1) & 1];
            const int ks1 = (st + 1) * 128 + srow;
            #pragma unroll
            for (int p = 0; p < 4; p++) {
                cp16(dstb + srow * ROWB + (sg + p) * 16,
                     k + bh + (size_t)ks1 * CD + (sg + p) * 8);
                cp16(dstb + KSTG_B + srow * ROWB + (sg + p) * 16,
                     v + bh + (size_t)ks1 * CD + (sg + p) * 8);
            }
        }
        CP_COMMIT();

        #pragma unroll
        for (int sub = 0; sub < 2; sub++) {
            const int ks = st * 128 + sub * 64;
            if (ks > qrow0 + 15) continue;
            const uint32_t sK = kvBase[st & 1] + (uint32_t)(sub * 64) * ROWB;
            const uint32_t sV = kvBase[st & 1] + KSTG_B + (uint32_t)(sub * 64) * ROWB;

            float sf[8][4];
            #pragma unroll
            for (int j = 0; j < 8; j++)
                #pragma unroll
                for (int t = 0; t < 4; t++) sf[j][t] = 0.f;
            #pragma unroll
            for (int kb = 0; kb < 4; kb++) {
                uint32_t bf[4][4];
                #pragma unroll
                for (int p = 0; p < 4; p++)
                    ldsm4(bf[p], sK + (uint32_t)(p * 16) * ROWB + bLd + kb * 32);
                #pragma unroll
                for (int j = 0; j < 8; j++)
                    mma_f16(sf[j], qf[kb], &bf[j >> 1][(j & 1) * 2]);
            }

            if (ks + 63 > qrow0) {
                const int qr0 = qrow0 + gid, qr1 = qr0 + 8;
                #pragma unroll
                for (int j = 0; j < 8; j++) {
                    const int kc = ks + j * 8 + 2 * tig;
                    if (kc > qr0)     sf[j][0] = -1e30f;
                    if (kc + 1 > qr0) sf[j][1] = -1e30f;
                    if (kc > qr1)     sf[j][2] = -1e30f;
                    if (kc + 1 > qr1) sf[j][3] = -1e30f;
                }
            }

            #pragma unroll
            for (int r = 0; r < 2; r++) {
                float mx = -1e30f;
                #pragma unroll
                for (int j = 0; j < 8; j++)
                    mx = fmaxf(mx, fmaxf(sf[j][2 * r], sf[j][2 * r + 1]));
                mx = fmaxf(mx, __shfl_xor_sync(0xffffffffu, mx, 1));
                mx = fmaxf(mx, __shfl_xor_sync(0xffffffffu, mx, 2));
                const float mnew = fmaxf(m[r], mx);
                const float alpha = exp2f(m[r] - mnew);
                float rs = 0.f;
                #pragma unroll
                for (int j = 0; j < 8; j++) {
                    float p0 = exp2f(sf[j][2 * r] - mnew);
                    float p1 = exp2f(sf[j][2 * r + 1] - mnew);
                    sf[j][2 * r] = p0; sf[j][2 * r + 1] = p1;
                    rs += p0 + p1;
                }
                rs += __shfl_xor_sync(0xffffffffu, rs, 1);
                rs += __shfl_xor_sync(0xffffffffu, rs, 2);
                l[r] = l[r] * alpha + rs;
                m[r] = mnew;
                #pragma unroll
                for (int j = 0; j < 8; j++) { o[j][2 * r] *= alpha; o[j][2 * r + 1] *= alpha; }
            }

            #pragma unroll
            for (int kb = 0; kb < 4; kb++) {
                uint32_t pa[4];
                pa[0] = packh2(sf[2 * kb][0],     sf[2 * kb][1]);
                pa[1] = packh2(sf[2 * kb][2],     sf[2 * kb][3]);
                pa[2] = packh2(sf[2 * kb + 1][0], sf[2 * kb + 1][1]);
                pa[3] = packh2(sf[2 * kb + 1][2], sf[2 * kb + 1][3]);
                uint32_t vf[4][4];
                #pragma unroll
                for (int p = 0; p < 4; p++)
                    ldsm4t(vf[p], sV + (uint32_t)(kb * 16) * ROWB + vLd + p * 32);
                #pragma unroll
                for (int j = 0; j < 8; j++)
                    mma_f16(o[j], pa, &vf[j >> 1][(j & 1) * 2]);
            }
        }
    }

    const float inv0 = 1.f / l[0], inv1 = 1.f / l[1];
    const int qa0 = qs + warp * 16 + gid, qa1 = qa0 + 8;
    #pragma unroll
    for (int j = 0; j < 8; j++) {
        const int cc = j * 8 + 2 * tig;
        *(uint32_t*)(y + bh + (size_t)qa0 * CD + cc) = packh2(o[j][0] * inv0, o[j][1] * inv0);
        *(uint32_t*)(y + bh + (size_t)qa1 * CD + cc) = packh2(o[j][2] * inv1, o[j][3] * inv1);
    }
}

// ---------------- launch ----------------
extern "C" void kernel_launch(void* const* d_in, const int* in_sizes, int n_in,
                              void* d_out, int out_size) {
    const float* x   = (const float*)d_in[0];
    const float* cs  = (const float*)d_in[1];
    const float* sn  = (const float*)d_in[2];
    const float* wq  = (const float*)d_in[3];
    const float* wk  = (const float*)d_in[4];
    const float* wv  = (const float*)d_in[5];
    const float* wo  = (const float*)d_in[6];
    const float* wfc = (const float*)d_in[7];
    const float* wpr = (const float*)d_in[8];
    const float* g1  = (const float*)d_in[9];
    const float* g2  = (const float*)d_in[10];
    float* out = (float*)d_out;

    __half *h, *q, *k, *v, *y, *ff;
    __half *wqt, *wkt, *wvt, *wot, *wfct, *wprt;
    float *x2;
    cudaGetSymbolAddress((void**)&h,  g_h);
    cudaGetSymbolAddress((void**)&q,  g_q);
    cudaGetSymbolAddress((void**)&k,  g_k);
    cudaGetSymbolAddress((void**)&v,  g_v);
    cudaGetSymbolAddress((void**)&y,  g_y);
    cudaGetSymbolAddress((void**)&ff, g_ff);
    cudaGetSymbolAddress((void**)&x2, g_x2);
    cudaGetSymbolAddress((void**)&wqt,  g_wqt);
    cudaGetSymbolAddress((void**)&wkt,  g_wkt);
    cudaGetSymbolAddress((void**)&wvt,  g_wvt);
    cudaGetSymbolAddress((void**)&wot,  g_wot);
    cudaGetSymbolAddress((void**)&wfct, g_wfct);
    cudaGetSymbolAddress((void**)&wprt, g_wprt);

    cudaFuncSetAttribute((const void*)attn_f16,
                         cudaFuncAttributeMaxDynamicSharedMemorySize, ATTN_SMEM);
    cudaFuncSetAttribute((const void*)qkv_gemm,
                         cudaFuncAttributeMaxDynamicSharedMemorySize, GEMM_SMEM);
    cudaFuncSetAttribute((const void*)gemm64_f16<1>,
                         cudaFuncAttributeMaxDynamicSharedMemorySize, GEMM64_SMEM);
    cudaFuncSetAttribute((const void*)gemm64_f16<2>,
                         cudaFuncAttributeMaxDynamicSharedMemorySize, GEMM64_SMEM);

    // 0+1. fused: weight transposes (z<6) + rmsnorm1 (z==6), co-resident
    prolog_all<<<dim3(96, 24, 7), 256>>>(wq, wk, wv, wo, wfc, wpr,
                                         wqt, wkt, wvt, wot, wfct, wprt,
                                         x, g1, h);

    // 2+3. q,k,v (BN=128 padded path, RoPE fused, q pre-scaled)
    qkv_gemm<<<dim3(18, 32), 256, GEMM_SMEM>>>(h, wqt, wkt, wvt, cs, sn, q, k, v);

    // 4. attention -> y (128-key stages, bh-fast grid)
    attn_f16<<<dim3(HH * BB, TT / 128), 256, ATTN_SMEM>>>(q, k, v, y);

    // 5. x2 = x + y @ wo
    gemm64_f16<1><<<dim3(CD / 64, NROWS / 128), 256, GEMM64_SMEM>>>(y, wot, x, x2, CD, CD);

    // 6. h = rmsnorm(x2, g2)
    rmsnorm_kernel<<<NROWS, 256>>>(x2, g2, h);

    // 7. ff = relu(h @ wfc)^2
    gemm64_f16<2><<<dim3(FFD / 64, NROWS / 128), 256, GEMM64_SMEM>>>(h, wfct, nullptr, ff, FFD, CD);

    // 8. out = x2 + ff @ wpr
    gemm64_f16<1><<<dim3(CD / 64, NROWS / 128), 256, GEMM64_SMEM>>>(ff, wprt, x2, out, CD, FFD);
}